// round 2
// baseline (speedup 1.0000x reference)
#include <cuda_runtime.h>
#include <math.h>

#define Bb      256
#define Nn      8192
#define SD      14
#define ROWS    256
#define THREADS 256
#define CHUNKS  (Nn / ROWS)   // 32

// accumulators: 0=sum werr[0:6], 1=sum werr[6:13], 2=sum werr[13],
//               3=sum residual^2, 4=sum quat, 5=sum massflow, 6=sum bc
__device__ double       g_acc[7];
__device__ int          g_tidx;
__device__ unsigned int g_done;

// ---------------------------------------------------------------------------
// Kernel 1: zero accumulators + argmin |t[0,:,0]| (high-MLP version)
// ---------------------------------------------------------------------------
__global__ void k_init(const float* __restrict__ t)
{
    const int tid = threadIdx.x;
    if (tid < 7) g_acc[tid] = 0.0;
    if (tid == 7) g_done = 0u;

    // each thread owns 32 contiguous elements = 8 independent float4 loads
    const float4* t4 = (const float4*)t;
    float4 v[8];
    #pragma unroll
    for (int j = 0; j < 8; j++) v[j] = t4[tid * 8 + j];

    float best = 3.402823466e+38f;
    int   bi   = 0;
    #pragma unroll
    for (int j = 0; j < 8; j++) {
        float a[4] = { fabsf(v[j].x), fabsf(v[j].y), fabsf(v[j].z), fabsf(v[j].w) };
        #pragma unroll
        for (int k = 0; k < 4; k++) {
            int idx = tid * 32 + j * 4 + k;
            if (a[k] < best) { best = a[k]; bi = idx; }   // first occurrence wins
        }
    }

    __shared__ float svals[THREADS];
    __shared__ int   sidx[THREADS];
    svals[tid] = best;
    sidx[tid]  = bi;
    __syncthreads();
    for (int s = THREADS / 2; s > 0; s >>= 1) {
        if (tid < s) {
            float v2 = svals[tid + s];
            int   i2 = sidx[tid + s];
            if (v2 < svals[tid] || (v2 == svals[tid] && i2 < sidx[tid])) {
                svals[tid] = v2;
                sidx[tid]  = i2;
            }
        }
        __syncthreads();
    }
    if (tid == 0) g_tidx = sidx[0];
}

// ---------------------------------------------------------------------------
// Kernel 2: fused loss reduction + last-block finalize.
// One block = 256 rows of one batch element. Only pred is staged in smem.
// ---------------------------------------------------------------------------
__global__ __launch_bounds__(THREADS)
void k_main(const float* __restrict__ pred,
            const float* __restrict__ truev,
            const float* __restrict__ t,
            const float* __restrict__ ctrl,
            float* __restrict__ out)
{
    // padded rows: 15 floats (stride 15 coprime with 32 banks -> conflict-free)
    __shared__ float  sp[(ROWS + 2) * 15];     // pred chunk + 2 halo rows
    __shared__ double red[THREADS / 32][7];

    const int b     = blockIdx.x >> 5;          // / CHUNKS
    const int chunk = blockIdx.x & (CHUNKS - 1);
    const int n0    = chunk * ROWS;
    const int tid   = threadIdx.x;

    const float* pbase = pred  + ((size_t)b * Nn + n0) * SD;
    const float* tbase = truev + ((size_t)b * Nn + n0) * SD;
    const float* cbase = ctrl  + ((size_t)b * Nn + n0) * 4;

    const int tidx = g_tidx;

    // ---- staging + streaming data/BC loss (float4, fully coalesced) ----
    float sA = 0.f, sB = 0.f, sC = 0.f, sBC = 0.f;
    {
        const float4* p4 = (const float4*)pbase;
        const float4* t4 = (const float4*)tbase;
        for (int i = tid; i < (ROWS * SD) / 4; i += THREADS) {     // 896 float4
            float4 p = p4[i];
            float4 tv = t4[i];
            const float pe[4] = { p.x, p.y, p.z, p.w };
            const float te[4] = { tv.x, tv.y, tv.z, tv.w };
            #pragma unroll
            for (int k = 0; k < 4; k++) {
                int e = 4 * i + k;
                int r = e / SD;
                int c = e - r * SD;
                sp[(r + 1) * 15 + c] = pe[k];
                float d  = pe[k] - te[k];
                float d2 = d * d;
                if (c < 6)        sA += d2;
                else if (c == 13) sC += d2;
                else              sB += d2;
                if (n0 + r == tidx) sBC += d2;
            }
        }
    }
    // halo rows
    if (n0 > 0 && tid < SD)
        sp[tid] = pbase[tid - SD];
    if (n0 + ROWS < Nn && tid >= 32 && tid < 32 + SD)
        sp[(ROWS + 1) * 15 + (tid - 32)] = pbase[ROWS * SD + (tid - 32)];
    __syncthreads();

    const int n = n0 + tid;                     // global time index, one row/thread
    const float* s = &sp[(tid + 1) * 15];

    // control row: coalesced per-thread float4
    const float4 u4 = ((const float4*)cbase)[tid];

    // ---- quaternion norm loss ----
    const float q0 = s[6], q1 = s[7], q2 = s[8], q3 = s[9];
    const float qn = sqrtf(q0 * q0 + q1 * q1 + q2 * q2 + q3 * q3);
    const float dqn = qn - 1.0f;
    const float sQ  = dqn * dqn;

    // ---- mass flow loss ----
    float sMF = 0.f;
    if (n < Nn - 1) {
        float dmf = sp[(tid + 2) * 15 + 13] - s[13];
        sMF = dmf > 0.f ? dmf : 0.f;
    }

    // ---- finite difference endpoints ----
    const float* lo;
    const float* hi;
    float dt;
    if (n == 0)           { lo = s;              hi = &sp[(tid + 2) * 15]; dt = t[1]      - t[0];      }
    else if (n == Nn - 1) { lo = &sp[tid * 15];  hi = s;                   dt = t[Nn - 1] - t[Nn - 2]; }
    else                  { lo = &sp[tid * 15];  hi = &sp[(tid + 2) * 15]; dt = t[n + 1]  - t[n - 1];  }
    const float inv_dt = 1.0f / (dt + 1e-12f);

    // ---- dynamics ----
    const float vx = s[3],  vy = s[4],  vz = s[5];
    const float wx = s[10], wy = s[11], wz = s[12];
    const float m  = s[13];

    const float thrust = u4.x * 1000000.0f;
    const float bzx = 2.0f * (q1 * q3 + q0 * q2);
    const float bzy = 2.0f * (q2 * q3 - q0 * q1);
    const float bzz = 1.0f - 2.0f * (q1 * q1 + q2 * q2);
    const float speed = sqrtf(vx * vx + vy * vy + vz * vz + 1e-12f);
    const float dragc = -0.30625f * speed;     // -0.5*rho*Cd*A*speed
    const float invm  = 1.0f / m;

    float dyn[SD];
    dyn[0]  = vx; dyn[1] = vy; dyn[2] = vz;
    dyn[3]  = (thrust * bzx + dragc * vx) * invm;
    dyn[4]  = (thrust * bzy + dragc * vy) * invm;
    dyn[5]  = (thrust * bzz + dragc * vz) * invm - 9.80665f;
    dyn[6]  = 0.5f * (-q1 * wx - q2 * wy - q3 * wz);
    dyn[7]  = 0.5f * ( q0 * wx + q2 * wz - q3 * wy);
    dyn[8]  = 0.5f * ( q0 * wy - q1 * wz + q3 * wx);
    dyn[9]  = 0.5f * ( q0 * wz + q1 * wy - q2 * wx);
    dyn[10] = (u4.y * 10000.0f + 4000.0f * wy * wz) * (1.0f / 5000.0f);
    dyn[11] = (u4.z * 10000.0f - 4000.0f * wz * wx) * (1.0f / 5000.0f);
    dyn[12] = (u4.w * 10000.0f) * (1.0f / 1000.0f);
    dyn[13] = -thrust * (1.0f / (300.0f * 9.80665f));

    float sP = 0.f;
    #pragma unroll
    for (int i = 0; i < SD; i++) {
        float r = (hi[i] - lo[i]) * inv_dt - dyn[i];
        sP += r * r;
    }

    // ---- reduction: fp32 intra-warp, fp64 cross-warp + global atomics ----
    float vf[7] = { sA, sB, sC, sP, sQ, sMF, sBC };
    const int lane = tid & 31, warp = tid >> 5;
    #pragma unroll
    for (int off = 16; off > 0; off >>= 1)
        #pragma unroll
        for (int j = 0; j < 7; j++)
            vf[j] += __shfl_down_sync(0xffffffffu, vf[j], off);
    if (lane == 0)
        #pragma unroll
        for (int j = 0; j < 7; j++) red[warp][j] = (double)vf[j];
    __syncthreads();

    if (warp == 0) {
        double vd[7];
        #pragma unroll
        for (int j = 0; j < 7; j++)
            vd[j] = (lane < THREADS / 32) ? red[lane][j] : 0.0;
        #pragma unroll
        for (int off = 4; off > 0; off >>= 1)
            #pragma unroll
            for (int j = 0; j < 7; j++)
                vd[j] += __shfl_down_sync(0xffffffffu, vd[j], off);
        if (lane == 0) {
            #pragma unroll
            for (int j = 0; j < 7; j++)
                atomicAdd(&g_acc[j], vd[j]);

            // ---- last block finalizes (threadFenceReduction pattern) ----
            __threadfence();
            unsigned int ticket = atomicAdd(&g_done, 1u);
            if (ticket == gridDim.x - 1) {
                const double BN = (double)Bb * (double)Nn;
                double L_data = g_acc[0] / (BN * 6.0) + g_acc[1] / (BN * 7.0)
                              + g_acc[2] / BN;
                double L_phys = g_acc[3] / (BN * 14.0);
                double L_quat = g_acc[4] / BN;
                double L_mf   = g_acc[5] / ((double)Bb * (double)(Nn - 1));
                double L_bc   = g_acc[6] / ((double)Bb * 14.0);
                double total  = L_data + 0.1 * L_phys + L_bc
                              + 0.01 * L_quat + 0.01 * L_mf;
                out[0] = (float)total;
                out[1] = (float)L_data;
                out[2] = (float)L_phys;
                out[3] = (float)L_bc;
                out[4] = (float)L_quat;
                out[5] = (float)L_mf;
            }
        }
    }
}

// ---------------------------------------------------------------------------
extern "C" void kernel_launch(void* const* d_in, const int* in_sizes, int n_in,
                              void* d_out, int out_size)
{
    const float* pred = (const float*)d_in[0];
    const float* tru  = (const float*)d_in[1];
    const float* t    = (const float*)d_in[2];
    const float* ctrl = (const float*)d_in[3];
    float* out = (float*)d_out;

    k_init<<<1, THREADS>>>(t);
    k_main<<<Bb * CHUNKS, THREADS>>>(pred, tru, t, ctrl, out);
}

// round 5
// speedup vs baseline: 1.0048x; 1.0048x over previous
#include <cuda_runtime.h>
#include <math.h>

#define Bb      256
#define Nn      8192
#define SD      14
#define ROWS    256
#define THREADS 256
#define CHUNKS  (Nn / ROWS)   // 32

// accumulators: 0=sum werr[0:6], 1=sum werr[6:13], 2=sum werr[13],
//               3=sum residual^2, 4=sum quat, 5=sum massflow, 6=sum bc
__device__ double       g_acc[7];
__device__ int          g_tidx;
__device__ unsigned int g_done;

// ---------------------------------------------------------------------------
// Kernel 1: zero accumulators + argmin |t[0,:,0]| (high-MLP version)
// ---------------------------------------------------------------------------
__global__ void k_init(const float* __restrict__ t)
{
    const int tid = threadIdx.x;
    if (tid < 7) g_acc[tid] = 0.0;
    if (tid == 7) g_done = 0u;

    // each thread owns 32 contiguous elements = 8 independent float4 loads
    const float4* t4 = (const float4*)t;
    float4 v[8];
    #pragma unroll
    for (int j = 0; j < 8; j++) v[j] = t4[tid * 8 + j];

    float best = 3.402823466e+38f;
    int   bi   = 0;
    #pragma unroll
    for (int j = 0; j < 8; j++) {
        float a[4] = { fabsf(v[j].x), fabsf(v[j].y), fabsf(v[j].z), fabsf(v[j].w) };
        #pragma unroll
        for (int k = 0; k < 4; k++) {
            int idx = tid * 32 + j * 4 + k;
            if (a[k] < best) { best = a[k]; bi = idx; }   // first occurrence wins
        }
    }

    __shared__ float svals[THREADS];
    __shared__ int   sidx[THREADS];
    svals[tid] = best;
    sidx[tid]  = bi;
    __syncthreads();
    for (int s = THREADS / 2; s > 0; s >>= 1) {
        if (tid < s) {
            float v2 = svals[tid + s];
            int   i2 = sidx[tid + s];
            if (v2 < svals[tid] || (v2 == svals[tid] && i2 < sidx[tid])) {
                svals[tid] = v2;
                sidx[tid]  = i2;
            }
        }
        __syncthreads();
    }
    if (tid == 0) g_tidx = sidx[0];
}

// ---------------------------------------------------------------------------
// Kernel 2: fused loss reduction + last-block finalize.
// One block = 256 rows of one batch element. Only pred is staged in smem.
// ---------------------------------------------------------------------------
__global__ __launch_bounds__(THREADS)
void k_main(const float* __restrict__ pred,
            const float* __restrict__ truev,
            const float* __restrict__ t,
            const float* __restrict__ ctrl,
            float* __restrict__ out)
{
    // padded rows: 15 floats (stride 15 coprime with 32 banks -> conflict-free)
    __shared__ float  sp[(ROWS + 2) * 15];     // pred chunk + 2 halo rows
    __shared__ double red[THREADS / 32][7];

    const int b     = blockIdx.x >> 5;          // / CHUNKS
    const int chunk = blockIdx.x & (CHUNKS - 1);
    const int n0    = chunk * ROWS;
    const int tid   = threadIdx.x;

    const float* pbase = pred  + ((size_t)b * Nn + n0) * SD;
    const float* tbase = truev + ((size_t)b * Nn + n0) * SD;
    const float* cbase = ctrl  + ((size_t)b * Nn + n0) * 4;

    const int tidx = g_tidx;

    // ---- staging + streaming data/BC loss (float4, fully coalesced) ----
    float sA = 0.f, sB = 0.f, sC = 0.f, sBC = 0.f;
    {
        const float4* p4 = (const float4*)pbase;
        const float4* t4 = (const float4*)tbase;
        for (int i = tid; i < (ROWS * SD) / 4; i += THREADS) {     // 896 float4
            float4 p = p4[i];
            float4 tv = t4[i];
            const float pe[4] = { p.x, p.y, p.z, p.w };
            const float te[4] = { tv.x, tv.y, tv.z, tv.w };
            #pragma unroll
            for (int k = 0; k < 4; k++) {
                int e = 4 * i + k;
                int r = e / SD;
                int c = e - r * SD;
                sp[(r + 1) * 15 + c] = pe[k];
                float d  = pe[k] - te[k];
                float d2 = d * d;
                if (c < 6)        sA += d2;
                else if (c == 13) sC += d2;
                else              sB += d2;
                if (n0 + r == tidx) sBC += d2;
            }
        }
    }
    // halo rows
    if (n0 > 0 && tid < SD)
        sp[tid] = pbase[tid - SD];
    if (n0 + ROWS < Nn && tid >= 32 && tid < 32 + SD)
        sp[(ROWS + 1) * 15 + (tid - 32)] = pbase[ROWS * SD + (tid - 32)];
    __syncthreads();

    const int n = n0 + tid;                     // global time index, one row/thread
    const float* s = &sp[(tid + 1) * 15];

    // control row: coalesced per-thread float4
    const float4 u4 = ((const float4*)cbase)[tid];

    // ---- quaternion norm loss ----
    const float q0 = s[6], q1 = s[7], q2 = s[8], q3 = s[9];
    const float qn = sqrtf(q0 * q0 + q1 * q1 + q2 * q2 + q3 * q3);
    const float dqn = qn - 1.0f;
    const float sQ  = dqn * dqn;

    // ---- mass flow loss ----
    float sMF = 0.f;
    if (n < Nn - 1) {
        float dmf = sp[(tid + 2) * 15 + 13] - s[13];
        sMF = dmf > 0.f ? dmf : 0.f;
    }

    // ---- finite difference endpoints ----
    const float* lo;
    const float* hi;
    float dt;
    if (n == 0)           { lo = s;              hi = &sp[(tid + 2) * 15]; dt = t[1]      - t[0];      }
    else if (n == Nn - 1) { lo = &sp[tid * 15];  hi = s;                   dt = t[Nn - 1] - t[Nn - 2]; }
    else                  { lo = &sp[tid * 15];  hi = &sp[(tid + 2) * 15]; dt = t[n + 1]  - t[n - 1];  }
    const float inv_dt = 1.0f / (dt + 1e-12f);

    // ---- dynamics ----
    const float vx = s[3],  vy = s[4],  vz = s[5];
    const float wx = s[10], wy = s[11], wz = s[12];
    const float m  = s[13];

    const float thrust = u4.x * 1000000.0f;
    const float bzx = 2.0f * (q1 * q3 + q0 * q2);
    const float bzy = 2.0f * (q2 * q3 - q0 * q1);
    const float bzz = 1.0f - 2.0f * (q1 * q1 + q2 * q2);
    const float speed = sqrtf(vx * vx + vy * vy + vz * vz + 1e-12f);
    const float dragc = -0.30625f * speed;     // -0.5*rho*Cd*A*speed
    const float invm  = 1.0f / m;

    float dyn[SD];
    dyn[0]  = vx; dyn[1] = vy; dyn[2] = vz;
    dyn[3]  = (thrust * bzx + dragc * vx) * invm;
    dyn[4]  = (thrust * bzy + dragc * vy) * invm;
    dyn[5]  = (thrust * bzz + dragc * vz) * invm - 9.80665f;
    dyn[6]  = 0.5f * (-q1 * wx - q2 * wy - q3 * wz);
    dyn[7]  = 0.5f * ( q0 * wx + q2 * wz - q3 * wy);
    dyn[8]  = 0.5f * ( q0 * wy - q1 * wz + q3 * wx);
    dyn[9]  = 0.5f * ( q0 * wz + q1 * wy - q2 * wx);
    dyn[10] = (u4.y * 10000.0f + 4000.0f * wy * wz) * (1.0f / 5000.0f);
    dyn[11] = (u4.z * 10000.0f - 4000.0f * wz * wx) * (1.0f / 5000.0f);
    dyn[12] = (u4.w * 10000.0f) * (1.0f / 1000.0f);
    dyn[13] = -thrust * (1.0f / (300.0f * 9.80665f));

    float sP = 0.f;
    #pragma unroll
    for (int i = 0; i < SD; i++) {
        float r = (hi[i] - lo[i]) * inv_dt - dyn[i];
        sP += r * r;
    }

    // ---- reduction: fp32 intra-warp, fp64 cross-warp + global atomics ----
    float vf[7] = { sA, sB, sC, sP, sQ, sMF, sBC };
    const int lane = tid & 31, warp = tid >> 5;
    #pragma unroll
    for (int off = 16; off > 0; off >>= 1)
        #pragma unroll
        for (int j = 0; j < 7; j++)
            vf[j] += __shfl_down_sync(0xffffffffu, vf[j], off);
    if (lane == 0)
        #pragma unroll
        for (int j = 0; j < 7; j++) red[warp][j] = (double)vf[j];
    __syncthreads();

    if (warp == 0) {
        double vd[7];
        #pragma unroll
        for (int j = 0; j < 7; j++)
            vd[j] = (lane < THREADS / 32) ? red[lane][j] : 0.0;
        #pragma unroll
        for (int off = 4; off > 0; off >>= 1)
            #pragma unroll
            for (int j = 0; j < 7; j++)
                vd[j] += __shfl_down_sync(0xffffffffu, vd[j], off);
        if (lane == 0) {
            #pragma unroll
            for (int j = 0; j < 7; j++)
                atomicAdd(&g_acc[j], vd[j]);

            // ---- last block finalizes (threadFenceReduction pattern) ----
            __threadfence();
            unsigned int ticket = atomicAdd(&g_done, 1u);
            if (ticket == gridDim.x - 1) {
                const double BN = (double)Bb * (double)Nn;
                double L_data = g_acc[0] / (BN * 6.0) + g_acc[1] / (BN * 7.0)
                              + g_acc[2] / BN;
                double L_phys = g_acc[3] / (BN * 14.0);
                double L_quat = g_acc[4] / BN;
                double L_mf   = g_acc[5] / ((double)Bb * (double)(Nn - 1));
                double L_bc   = g_acc[6] / ((double)Bb * 14.0);
                double total  = L_data + 0.1 * L_phys + L_bc
                              + 0.01 * L_quat + 0.01 * L_mf;
                out[0] = (float)total;
                out[1] = (float)L_data;
                out[2] = (float)L_phys;
                out[3] = (float)L_bc;
                out[4] = (float)L_quat;
                out[5] = (float)L_mf;
            }
        }
    }
}

// ---------------------------------------------------------------------------
extern "C" void kernel_launch(void* const* d_in, const int* in_sizes, int n_in,
                              void* d_out, int out_size)
{
    const float* pred = (const float*)d_in[0];
    const float* tru  = (const float*)d_in[1];
    const float* t    = (const float*)d_in[2];
    const float* ctrl = (const float*)d_in[3];
    float* out = (float*)d_out;

    k_init<<<1, THREADS>>>(t);
    k_main<<<Bb * CHUNKS, THREADS>>>(pred, tru, t, ctrl, out);
}

// round 6
// speedup vs baseline: 1.5102x; 1.5030x over previous
#include <cuda_runtime.h>
#include <math.h>

#define Bb      256
#define Nn      8192
#define SD      14
#define ROWS    256
#define THREADS 256
#define CHUNKS  32
#define NTILES  (Bb * CHUNKS)        // 8192
#define GRID    444                  // 148 SMs * 3 resident blocks

#define TILE_F4      ((ROWS * SD) / 4)   // 896
#define MAIN_FLOATS  (ROWS * SD)         // 3584
#define HALO_LO_OFF  MAIN_FLOATS         // 3584 (14 floats)
#define HALO_HI_OFF  (MAIN_FLOATS + 14)  // 3598 (14 floats)
#define BUF_FLOATS   3616                // padded, 16B-multiple

// accumulators: 0=weighted data, 1=phys, 2=quat, 3=massflow, 4=bc
__device__ double       g_acc[5];
__device__ int          g_tidx;
__device__ unsigned int g_done;

// ---------------------------------------------------------------------------
// cp.async helpers
// ---------------------------------------------------------------------------
__device__ __forceinline__ void cp16(void* smem_dst, const void* gsrc) {
    unsigned sa = (unsigned)__cvta_generic_to_shared(smem_dst);
    asm volatile("cp.async.cg.shared.global [%0], [%1], 16;\n" :: "r"(sa), "l"(gsrc));
}
__device__ __forceinline__ void cp4(void* smem_dst, const void* gsrc) {
    unsigned sa = (unsigned)__cvta_generic_to_shared(smem_dst);
    asm volatile("cp.async.ca.shared.global [%0], [%1], 4;\n" :: "r"(sa), "l"(gsrc));
}
#define CP_COMMIT() asm volatile("cp.async.commit_group;\n" ::: "memory")
#define CP_WAIT0()  asm volatile("cp.async.wait_group 0;\n" ::: "memory")

// ---------------------------------------------------------------------------
// Kernel 1: zero accumulators + argmin |t[0,:,0]|
// ---------------------------------------------------------------------------
__global__ void k_init(const float* __restrict__ t)
{
    const int tid = threadIdx.x;
    if (tid < 5) g_acc[tid] = 0.0;
    if (tid == 5) g_done = 0u;

    const float4* t4 = (const float4*)t;
    float4 v[8];
    #pragma unroll
    for (int j = 0; j < 8; j++) v[j] = t4[tid * 8 + j];

    float best = 3.402823466e+38f;
    int   bi   = 0;
    #pragma unroll
    for (int j = 0; j < 8; j++) {
        float a[4] = { fabsf(v[j].x), fabsf(v[j].y), fabsf(v[j].z), fabsf(v[j].w) };
        #pragma unroll
        for (int k = 0; k < 4; k++) {
            int idx = tid * 32 + j * 4 + k;
            if (a[k] < best) { best = a[k]; bi = idx; }
        }
    }

    __shared__ float svals[THREADS];
    __shared__ int   sidx[THREADS];
    svals[tid] = best;  sidx[tid] = bi;
    __syncthreads();
    for (int s = THREADS / 2; s > 0; s >>= 1) {
        if (tid < s) {
            float v2 = svals[tid + s];
            int   i2 = sidx[tid + s];
            if (v2 < svals[tid] || (v2 == svals[tid] && i2 < sidx[tid])) {
                svals[tid] = v2;  sidx[tid] = i2;
            }
        }
        __syncthreads();
    }
    if (tid == 0) g_tidx = sidx[0];
}

// ---------------------------------------------------------------------------
// issue cp.async loads for one tile (pred main + halos) into buffer
// ---------------------------------------------------------------------------
__device__ __forceinline__ void issue_tile(int tile, float* buf,
                                           const float* __restrict__ pred,
                                           int tid)
{
    const int b = tile >> 5, chunk = tile & (CHUNKS - 1);
    const float* pbase = pred + ((size_t)b * Nn + (size_t)chunk * ROWS) * SD;
    const float4* p4 = (const float4*)pbase;
    float4* b4 = (float4*)buf;

    cp16(b4 + tid,       p4 + tid);
    cp16(b4 + tid + 256, p4 + tid + 256);
    cp16(b4 + tid + 512, p4 + tid + 512);
    if (tid < TILE_F4 - 768) cp16(b4 + tid + 768, p4 + tid + 768);

    if (chunk > 0 && tid >= 128 && tid < 128 + SD)
        cp4(buf + HALO_LO_OFF + (tid - 128), pbase - SD + (tid - 128));
    if (chunk < CHUNKS - 1 && tid >= 160 && tid < 160 + SD)
        cp4(buf + HALO_HI_OFF + (tid - 160), pbase + MAIN_FLOATS + (tid - 160));

    CP_COMMIT();
}

// ---------------------------------------------------------------------------
// Kernel 2: persistent fused loss reduction + last-block finalize
// ---------------------------------------------------------------------------
__global__ __launch_bounds__(THREADS, 3)
void k_main(const float* __restrict__ pred,
            const float* __restrict__ truev,
            const float* __restrict__ t,
            const float* __restrict__ ctrl,
            float* __restrict__ out)
{
    __shared__ __align__(16) float sbuf[2][BUF_FLOATS];
    __shared__ double red[THREADS / 32][5];

    const int tid  = threadIdx.x;
    const int tidx = g_tidx;

    float wD = 0.f, sP = 0.f, sQ = 0.f, sMF = 0.f, sBC = 0.f;

    int tile = blockIdx.x;
    issue_tile(tile, sbuf[0], pred, tid);
    int parity = 0;

    for (; tile < NTILES; tile += GRID) {
        CP_WAIT0();
        __syncthreads();

        const int next = tile + GRID;
        if (next < NTILES) issue_tile(next, sbuf[parity ^ 1], pred, tid);

        const float* buf = sbuf[parity];
        const int b = tile >> 5, chunk = tile & (CHUNKS - 1);
        const int n0 = chunk * ROWS;
        const size_t rowoff = (size_t)b * Nn + n0;

        // control row: coalesced per-thread float4 (demand load, hoisted early)
        const float4 u4 = ((const float4*)(ctrl + rowoff * 4))[tid];

        // ---- data loss (+BC) from staged pred + streamed true ----
        {
            const float4* t4  = (const float4*)(truev + rowoff * SD);
            const float4* bp4 = (const float4*)buf;
            #pragma unroll
            for (int j = 0; j < 4; j++) {
                const int i = tid + j * 256;
                if (j == 3 && i >= TILE_F4) break;
                float4 tv = t4[i];
                float4 pv = bp4[i];
                unsigned e = 4u * (unsigned)i;
                unsigned r = e / 14u;
                unsigned c = e - r * 14u;
                const float pe[4] = { pv.x, pv.y, pv.z, pv.w };
                const float te[4] = { tv.x, tv.y, tv.z, tv.w };
                #pragma unroll
                for (int k = 0; k < 4; k++) {
                    float d  = pe[k] - te[k];
                    float d2 = d * d;
                    float w  = (c < 6u) ? (1.0f / 6.0f)
                             : ((c == 13u) ? 1.0f : (1.0f / 7.0f));
                    wD = fmaf(d2, w, wD);
                    if ((int)(n0 + r) == tidx) sBC += d2;
                    if (++c == 14u) { c = 0u; ++r; }
                }
            }
        }

        // ---- per-row physics ----
        const int n = n0 + tid;
        const float* s = buf + tid * SD;

        float sr[SD];
        {
            const float2* s2 = (const float2*)s;
            #pragma unroll
            for (int k = 0; k < 7; k++) {
                float2 v = s2[k];
                sr[2 * k] = v.x;  sr[2 * k + 1] = v.y;
            }
        }

        const bool fwd = (n == 0), bwd = (n == Nn - 1);
        const float* hip = (tid < ROWS - 1) ? (buf + (tid + 1) * SD)
                                            : (buf + HALO_HI_OFF);
        const float* lop = (tid > 0)        ? (buf + (tid - 1) * SD)
                                            : (buf + HALO_LO_OFF);
        if (fwd) lop = s;
        if (bwd) hip = s;

        float ta, tb2;
        if (fwd)      { ta = t[0];      tb2 = t[1];      }
        else if (bwd) { ta = t[Nn - 2]; tb2 = t[Nn - 1]; }
        else          { ta = t[n - 1];  tb2 = t[n + 1];  }
        const float inv_dt = 1.0f / (tb2 - ta + 1e-12f);

        // quaternion norm loss
        const float q0 = sr[6], q1 = sr[7], q2 = sr[8], q3 = sr[9];
        const float qn  = sqrtf(q0 * q0 + q1 * q1 + q2 * q2 + q3 * q3);
        const float dqn = qn - 1.0f;
        sQ += dqn * dqn;

        // mass flow loss (n .. n+1), hip[13] == m[n+1] whenever n < Nn-1
        if (n < Nn - 1) {
            float dmf = hip[13] - sr[13];
            if (dmf > 0.f) sMF += dmf;
        }

        // dynamics
        const float vx = sr[3],  vy = sr[4],  vz = sr[5];
        const float wx = sr[10], wy = sr[11], wz = sr[12];
        const float thrust = u4.x * 1000000.0f;
        const float bzx = 2.0f * (q1 * q3 + q0 * q2);
        const float bzy = 2.0f * (q2 * q3 - q0 * q1);
        const float bzz = 1.0f - 2.0f * (q1 * q1 + q2 * q2);
        const float speed = sqrtf(vx * vx + vy * vy + vz * vz + 1e-12f);
        const float dragc = -0.30625f * speed;
        const float invm  = 1.0f / sr[13];

        float dyn[SD];
        dyn[0]  = vx; dyn[1] = vy; dyn[2] = vz;
        dyn[3]  = (thrust * bzx + dragc * vx) * invm;
        dyn[4]  = (thrust * bzy + dragc * vy) * invm;
        dyn[5]  = (thrust * bzz + dragc * vz) * invm - 9.80665f;
        dyn[6]  = 0.5f * (-q1 * wx - q2 * wy - q3 * wz);
        dyn[7]  = 0.5f * ( q0 * wx + q2 * wz - q3 * wy);
        dyn[8]  = 0.5f * ( q0 * wy - q1 * wz + q3 * wx);
        dyn[9]  = 0.5f * ( q0 * wz + q1 * wy - q2 * wx);
        dyn[10] = (u4.y * 10000.0f + 4000.0f * wy * wz) * (1.0f / 5000.0f);
        dyn[11] = (u4.z * 10000.0f - 4000.0f * wz * wx) * (1.0f / 5000.0f);
        dyn[12] = (u4.w * 10000.0f) * (1.0f / 1000.0f);
        dyn[13] = -thrust * (1.0f / (300.0f * 9.80665f));

        float sPl = 0.f;
        #pragma unroll
        for (int i = 0; i < SD; i++) {
            float rr = (hip[i] - lop[i]) * inv_dt - dyn[i];
            sPl = fmaf(rr, rr, sPl);
        }
        sP += sPl;

        parity ^= 1;
    }

    // ---- reduction: fp32 intra-warp, fp64 cross-warp + global atomics ----
    float vf[5] = { wD, sP, sQ, sMF, sBC };
    const int lane = tid & 31, warp = tid >> 5;
    #pragma unroll
    for (int off = 16; off > 0; off >>= 1)
        #pragma unroll
        for (int j = 0; j < 5; j++)
            vf[j] += __shfl_down_sync(0xffffffffu, vf[j], off);
    if (lane == 0)
        #pragma unroll
        for (int j = 0; j < 5; j++) red[warp][j] = (double)vf[j];
    __syncthreads();

    if (warp == 0) {
        double vd[5];
        #pragma unroll
        for (int j = 0; j < 5; j++)
            vd[j] = (lane < THREADS / 32) ? red[lane][j] : 0.0;
        #pragma unroll
        for (int off = 4; off > 0; off >>= 1)
            #pragma unroll
            for (int j = 0; j < 5; j++)
                vd[j] += __shfl_down_sync(0xffffffffu, vd[j], off);
        if (lane == 0) {
            #pragma unroll
            for (int j = 0; j < 5; j++)
                atomicAdd(&g_acc[j], vd[j]);

            __threadfence();
            unsigned int ticket = atomicAdd(&g_done, 1u);
            if (ticket == gridDim.x - 1) {
                const double BN = (double)Bb * (double)Nn;
                double L_data = g_acc[0] / BN;
                double L_phys = g_acc[1] / (BN * 14.0);
                double L_quat = g_acc[2] / BN;
                double L_mf   = g_acc[3] / ((double)Bb * (double)(Nn - 1));
                double L_bc   = g_acc[4] / ((double)Bb * 14.0);
                double total  = L_data + 0.1 * L_phys + L_bc
                              + 0.01 * L_quat + 0.01 * L_mf;
                out[0] = (float)total;
                out[1] = (float)L_data;
                out[2] = (float)L_phys;
                out[3] = (float)L_bc;
                out[4] = (float)L_quat;
                out[5] = (float)L_mf;
            }
        }
    }
}

// ---------------------------------------------------------------------------
extern "C" void kernel_launch(void* const* d_in, const int* in_sizes, int n_in,
                              void* d_out, int out_size)
{
    const float* pred = (const float*)d_in[0];
    const float* tru  = (const float*)d_in[1];
    const float* t    = (const float*)d_in[2];
    const float* ctrl = (const float*)d_in[3];
    float* out = (float*)d_out;

    k_init<<<1, THREADS>>>(t);
    k_main<<<GRID, THREADS>>>(pred, tru, t, ctrl, out);
}